// round 11
// baseline (speedup 1.0000x reference)
#include <cuda_runtime.h>

#define CHN   4
#define HHT   128
#define WWD   128
#define TT    50
#define TP    52          // padded t-stride: mult of 4 (LDS.128), conflict-free
#define SOP   52          // staging row stride (floats), float2 aligned
#define NBATCH 8
#define NPIX  (NBATCH*CHN*HHT*WWD)
#define AW2   132         // bufA plane width/height (PAD=2 halo)
#define BW2   130         // bufB plane width/height (PAD=1 halo)
#define NPLANE (NBATCH*CHN)   // 32

// Padded ping-pong buffers: [plane][H2][W2][TT], zero halo.
__device__ float g_bufA[NPLANE * AW2 * AW2 * TT];
__device__ float g_bufB[NPLANE * BW2 * BW2 * TT];

typedef unsigned long long u64;

// Pre-duplicated weights in constant memory.
// c_w5d[tap*2+0]=(w0,w0,w1,w1), [tap*2+1]=(w2,w2,w3,w3), tap=(ci*K+kh)*K+kw
__constant__ ulonglong2 c_w5d[200];
__constant__ ulonglong2 c_w3d[72];
__device__ float4 g_wpack[272];

template <int K>
__device__ __forceinline__ ulonglong2 cwload(int i);
template <>
__device__ __forceinline__ ulonglong2 cwload<5>(int i) { return c_w5d[i]; }
template <>
__device__ __forceinline__ ulonglong2 cwload<3>(int i) { return c_w3d[i]; }

__device__ __forceinline__ void fma2(u64& d, u64 a, u64 b) {
    asm("fma.rn.f32x2 %0, %1, %2, %0;" : "+l"(d) : "l"(a), "l"(b));
}
__device__ __forceinline__ float2 upk(u64 v) {
    float2 f;
    f.x = __uint_as_float((unsigned)(v & 0xffffffffull));
    f.y = __uint_as_float((unsigned)(v >> 32));
    return f;
}

__global__ void repack_kernel(const float* __restrict__ w1,
                              const float* __restrict__ w2) {
    int tid = threadIdx.x;
    if (tid < 100) {
        float a = w1[tid], b = w1[100 + tid], c = w1[200 + tid], d = w1[300 + tid];
        g_wpack[tid * 2 + 0] = make_float4(a, a, b, b);
        g_wpack[tid * 2 + 1] = make_float4(c, c, d, d);
    }
    if (tid >= 128 && tid < 164) {
        int t = tid - 128;
        float a = w2[t], b = w2[36 + t], c = w2[72 + t], d = w2[108 + t];
        g_wpack[200 + t * 2 + 0] = make_float4(a, a, b, b);
        g_wpack[200 + t * 2 + 1] = make_float4(c, c, d, d);
    }
}

// Zero the spatial halos of both padded buffers (cheap; graph-captured).
__global__ void zero_borders() {
    float* buf;
    int W2, P, plane;
    if (blockIdx.x < NPLANE) { buf = g_bufA; W2 = AW2; P = 2; plane = blockIdx.x; }
    else                     { buf = g_bufB; W2 = BW2; P = 1; plane = blockIdx.x - NPLANE; }
    const int H2 = W2;
    const int strip = 2 * P * W2;
    const int total = strip + 2 * P * (H2 - 2 * P);
    for (int idx = threadIdx.x; idx < total; idx += blockDim.x) {
        int h, w;
        if (idx < strip) {
            int r = idx / W2;
            w = idx - r * W2;
            h = (r < P) ? r : H2 - 2 * P + r;
        } else {
            int j = idx - strip;
            int c = j / (H2 - 2 * P);
            h = P + (j - c * (H2 - 2 * P));
            w = (c < P) ? c : W2 - 2 * P + c;
        }
        float* p = buf + (((long)plane * H2 + h) * W2 + w) * TT;
#pragma unroll
        for (int t = 0; t < TT; ++t) p[t] = 0.f;
    }
}

// ---------------------------------------------------------------------------
// Standalone alpha-PSP (layer 1): unpadded input -> padded bufA interior.
// Block = 4 warps, one (nc, h) row; warp handles its 32-wide w chunk.
// ---------------------------------------------------------------------------
#define PW_PAD 53

__global__ void __launch_bounds__(128, 8) psp_kernel(const float* __restrict__ in,
                                                     float* __restrict__ out,
                                                     float r, float coef) {
    __shared__ float sm[4 * 32 * PW_PAD];
    const int lane = threadIdx.x & 31;
    const int wrp  = threadIdx.x >> 5;
    const int h    = blockIdx.x;
    const int nc   = blockIdx.y;
    float* ws = sm + wrp * 32 * PW_PAD;
    const float* g = in + (((long)nc * HHT + h) * WWD + wrp * 32) * TT;
    float* o = out + (((long)nc * AW2 + h + 2) * AW2 + (wrp * 32 + 2)) * TT;
#pragma unroll
    for (int w = 0; w < 32; ++w) {
        ws[w * PW_PAD + lane] = g[w * TT + lane];
        if (lane < TT - 32) ws[w * PW_PAD + 32 + lane] = g[w * TT + 32 + lane];
    }
    __syncwarp();
    float* row = ws + lane * PW_PAD;
    float s1 = 0.f, s2 = 0.f;
#pragma unroll
    for (int t = 0; t < TT; ++t) {
        float x = row[t];
        row[t] = coef * s2;
        s1 = fmaf(r, s1, x);
        s2 = fmaf(r, s2, r * s1);
    }
    __syncwarp();
#pragma unroll
    for (int w = 0; w < 32; ++w) {
        o[w * TT + lane] = ws[w * PW_PAD + lane];
        if (lane < TT - 32) o[w * TT + 32 + lane] = ws[w * PW_PAD + 32 + lane];
    }
}

// ---------------------------------------------------------------------------
// Fused conv(KxK, 4->4) + spike epilogue, cp.async double-buffered, reading a
// zero-padded input plane -> ALL fill cp.asyncs are unconditional (no bounds
// predicates / clamps: the halo provides the zeros).
// Block (32w, h, n), 416 thr = 13 warps, thread = (w=lane, t-quad t0=4*wrp).
// EPI=0: spike + next-layer psp -> padded OUT. EPI=1: spike -> unpadded OUT.
// ---------------------------------------------------------------------------
template <int K, int EPI, int INW2, int OUTW2, int OUTPAD>
__global__ void __launch_bounds__(416, 3)
conv_fused_kernel(const float* __restrict__ in, float* __restrict__ out,
                  float rR, float cR, float theta, float rP, float cP) {
    constexpr int WH    = 32 + (K - 1);   // padded coords: rows w0..w0+WH-1
    constexpr int STAGE = K * WH * TP;

    extern __shared__ float sm[];
    const unsigned smem_base = (unsigned)__cvta_generic_to_shared(sm);

    const int tid  = threadIdx.x;
    const int lane = tid & 31;
    const int wrp  = tid >> 5;
    const int w0   = blockIdx.x * 32;
    const int h    = blockIdx.y;
    const int n    = blockIdx.z;
    const int t0   = wrp * 4;

    // unconditional async fill of one stage with channel ci
    auto fill = [&](int buf, int ci) {
        if (lane < 25) {
            const unsigned dstb = smem_base + buf * (STAGE * 4) + lane * 8;
            const int nc = n * CHN + ci;
#pragma unroll
            for (int kh = 0; kh < K; ++kh) {
                const char* srcb = (const char*)(in +
                    (((long)nc * INW2 + h + kh) * INW2 + w0) * TT) + lane * 8;
#pragma unroll
                for (int rr = 0; rr < 3; ++rr) {
                    const int row = wrp + rr * 13;
                    if (row < WH) {
                        asm volatile("cp.async.ca.shared.global [%0], [%1], 8;"
                                     :: "r"(dstb + (kh * WH + row) * (TP * 4)),
                                        "l"(srcb + row * (TT * 4)) : "memory");
                    }
                }
            }
        }
        asm volatile("cp.async.commit_group;" ::: "memory");
    };

    u64 acc[4][2];   // [co][(t0,t0+1)|(t0+2,t0+3)]
#pragma unroll
    for (int c = 0; c < 4; ++c) { acc[c][0] = 0ull; acc[c][1] = 0ull; }

    fill(0, 0);
    asm volatile("cp.async.wait_group 0;" ::: "memory");
    __syncthreads();

#pragma unroll
    for (int ci = 0; ci < CHN; ++ci) {
        if (ci < CHN - 1) fill((ci + 1) & 1, ci + 1);
        const float* s_in = sm + (ci & 1) * STAGE;
#pragma unroll
        for (int kh = 0; kh < K; ++kh) {
            const float* rowp = s_in + (kh * WH + lane) * TP + t0;
#pragma unroll
            for (int kw = 0; kw < K; ++kw) {
                const int tap = (ci * K + kh) * K + kw;
                const ulonglong2 iv = *reinterpret_cast<const ulonglong2*>(rowp + kw * TP);
                const ulonglong2 wa = cwload<K>(tap * 2);
                const ulonglong2 wb = cwload<K>(tap * 2 + 1);
                fma2(acc[0][0], iv.x, wa.x);
                fma2(acc[0][1], iv.y, wa.x);
                fma2(acc[1][0], iv.x, wa.y);
                fma2(acc[1][1], iv.y, wa.y);
                fma2(acc[2][0], iv.x, wb.x);
                fma2(acc[2][1], iv.y, wb.x);
                fma2(acc[3][0], iv.x, wb.y);
                fma2(acc[3][1], iv.y, wb.y);
            }
        }
        if (ci < CHN - 1) {
            asm volatile("cp.async.wait_group 0;" ::: "memory");
            __syncthreads();
        }
    }
    __syncthreads();

    // stage conv results: s_out[co][w][SOP], float2 stores
    float* s_out = sm;   // overlay: 4*32*52*4 = 26.6KB < 2*STAGE
#pragma unroll
    for (int co = 0; co < 4; ++co) {
        float* p = s_out + (co * 32 + lane) * SOP + t0;
        float2 a = upk(acc[co][0]);
        *reinterpret_cast<float2*>(p) = a;
        if (t0 + 2 < TT) {
            float2 b = upk(acc[co][1]);
            *reinterpret_cast<float2*>(p + 2) = b;
        }
    }
    __syncthreads();

    // fused spike-dynamics epilogue: 128 pixels (4co x 32w)
    if (tid < 128) {
        const int co = tid >> 5;
        const int w  = tid & 31;
        float* row = s_out + (co * 32 + w) * SOP;
        float sd1 = 0.f, sd2 = 0.f, sp1 = 0.f, sp2 = 0.f;
#pragma unroll
        for (int t = 0; t < TT; ++t) {
            float m = fmaf(cR, sd2, row[t]);
            float s = (m >= theta) ? 1.f : 0.f;
            sd1 = fmaf(rR, sd1, s);
            sd2 = fmaf(rR, sd2, rR * sd1);
            if (EPI == 0) {
                row[t] = cP * sp2;
                sp1 = fmaf(rP, sp1, s);
                sp2 = fmaf(rP, sp2, rP * sp1);
            } else {
                row[t] = s;
            }
        }
    }
    __syncthreads();

    // structured coalesced store: float2, warp-per-w-row (padded or flat out)
    if (lane < 25) {
#pragma unroll
        for (int co = 0; co < 4; ++co) {
            const float2* s2 = reinterpret_cast<const float2*>(s_out + co * 32 * SOP);
            float2* g2 = reinterpret_cast<float2*>(out +
                (((long)(n * CHN + co) * OUTW2 + h + OUTPAD) * OUTW2 + (w0 + OUTPAD)) * TT);
#pragma unroll
            for (int rr = 0; rr < 3; ++rr) {
                const int w = wrp + rr * 13;
                if (w < 32) g2[w * (TT / 2) + lane] = s2[w * (SOP / 2) + lane];
            }
        }
    }
}

// ---------------------------------------------------------------------------

extern "C" void kernel_launch(void* const* d_in, const int* in_sizes, int n_in,
                              void* d_out, int out_size) {
    const float* x  = (const float*)d_in[0];
    const float* w1 = (const float*)d_in[1];
    const float* w2 = (const float*)d_in[2];
    float* outp = (float*)d_out;

    float *bufA, *bufB;
    cudaGetSymbolAddress((void**)&bufA, g_bufA);
    cudaGetSymbolAddress((void**)&bufB, g_bufB);
    float4* wpack;
    cudaGetSymbolAddress((void**)&wpack, g_wpack);

    const int SMEM5 = 2 * 5 * 36 * TP * 4;   // 74880 B -> 3 blocks/SM
    const int SMEM3 = 2 * 3 * 34 * TP * 4;   // 42432 B -> 3 blocks/SM
    cudaFuncSetAttribute((const void*)conv_fused_kernel<5, 0, AW2, BW2, 1>,
                         cudaFuncAttributeMaxDynamicSharedMemorySize, SMEM5);
    cudaFuncSetAttribute((const void*)conv_fused_kernel<3, 1, BW2, WWD, 0>,
                         cudaFuncAttributeMaxDynamicSharedMemorySize, SMEM3);

    const float r1  = (float)0.36787944117144233;   // exp(-1/tau1)
    const float cP1 = (float)2.718281828459045;     // e/tau1
    const float rR1 = (float)0.36787944117144233;   // exp(-1/tauRef1)
    const float cR1 = (float)(-54.365636569180902); // -scaleRef*theta1*e/tauRef1
    const float th1 = 20.0f;
    const float r2  = (float)0.6065306597126334;    // exp(-1/tau2)
    const float cP2 = (float)1.3591409142295225;    // e/tau2
    const float rR2 = (float)0.6065306597126334;    // exp(-1/tauRef2)
    const float cR2 = (float)(-54.365636569180902); // -scaleRef*theta2*e/tauRef2
    const float th2 = 40.0f;

    dim3 pgrid(HHT, NPLANE);                    // (128, 32)
    dim3 cgrid(WWD / 32, HHT, NBATCH);          // (4,128,8)

    repack_kernel<<<1, 256>>>(w1, w2);
    cudaMemcpyToSymbolAsync(c_w5d, wpack, 200 * sizeof(float4), 0,
                            cudaMemcpyDeviceToDevice, 0);
    cudaMemcpyToSymbolAsync(c_w3d, wpack + 200, 72 * sizeof(float4), 0,
                            cudaMemcpyDeviceToDevice, 0);
    zero_borders<<<2 * NPLANE, 256>>>();

    psp_kernel<<<pgrid, 128>>>(x, bufA, r1, cP1);
    conv_fused_kernel<5, 0, AW2, BW2, 1><<<cgrid, 416, SMEM5>>>(bufA, bufB,
                                                    rR1, cR1, th1, r2, cP2);
    conv_fused_kernel<3, 1, BW2, WWD, 0><<<cgrid, 416, SMEM3>>>(bufB, outp,
                                                    rR2, cR2, th2, 0.f, 0.f);
}

// round 12
// speedup vs baseline: 1.2243x; 1.2243x over previous
#include <cuda_runtime.h>

#define CHN   4
#define HHT   128
#define WWD   128
#define TT    50
#define TP    52          // padded t-stride: mult of 4 (LDS.128), conflict-free
#define SOP   52          // staging row stride (floats), float2 aligned
#define NBATCH 8
#define AW2   132         // bufA plane width/height (PAD=2 halo)
#define BW2   130         // bufB plane width/height (PAD=1 halo)
#define NPLANE (NBATCH*CHN)   // 32

// Padded ping-pong buffers: [plane][H2][W2][TT], zero halo.
__device__ float g_bufA[NPLANE * AW2 * AW2 * TT];
__device__ float g_bufB[NPLANE * BW2 * BW2 * TT];

typedef unsigned long long u64;

// Pre-duplicated weights in constant memory.
// c_w5d[tap*2+0]=(w0,w0,w1,w1), [tap*2+1]=(w2,w2,w3,w3), tap=(ci*K+kh)*K+kw
__constant__ ulonglong2 c_w5d[200];
__constant__ ulonglong2 c_w3d[72];
__device__ float4 g_wpack[272];

template <int K>
__device__ __forceinline__ ulonglong2 cwload(int i);
template <>
__device__ __forceinline__ ulonglong2 cwload<5>(int i) { return c_w5d[i]; }
template <>
__device__ __forceinline__ ulonglong2 cwload<3>(int i) { return c_w3d[i]; }

__device__ __forceinline__ void fma2(u64& d, u64 a, u64 b) {
    asm("fma.rn.f32x2 %0, %1, %2, %0;" : "+l"(d) : "l"(a), "l"(b));
}
__device__ __forceinline__ float2 upk(u64 v) {
    float2 f;
    f.x = __uint_as_float((unsigned)(v & 0xffffffffull));
    f.y = __uint_as_float((unsigned)(v >> 32));
    return f;
}

__global__ void repack_kernel(const float* __restrict__ w1,
                              const float* __restrict__ w2) {
    int tid = threadIdx.x;
    if (tid < 100) {
        float a = w1[tid], b = w1[100 + tid], c = w1[200 + tid], d = w1[300 + tid];
        g_wpack[tid * 2 + 0] = make_float4(a, a, b, b);
        g_wpack[tid * 2 + 1] = make_float4(c, c, d, d);
    }
    if (tid >= 128 && tid < 164) {
        int t = tid - 128;
        float a = w2[t], b = w2[36 + t], c = w2[72 + t], d = w2[108 + t];
        g_wpack[200 + t * 2 + 0] = make_float4(a, a, b, b);
        g_wpack[200 + t * 2 + 1] = make_float4(c, c, d, d);
    }
}

// Zero the spatial halos (coalesced float2). One block per plane per buffer.
__global__ void zero_borders() {
    float* buf;
    int W2, P;
    int plane;
    if (blockIdx.x < NPLANE) { buf = g_bufA; W2 = AW2; P = 2; plane = blockIdx.x; }
    else                     { buf = g_bufB; W2 = BW2; P = 1; plane = blockIdx.x - NPLANE; }
    const int H2 = W2;
    float2* base = reinterpret_cast<float2*>(buf + (long)plane * H2 * W2 * TT);
    const int strip = P * W2 * TT / 2;        // one P-row strip in float2
    const float2 z = make_float2(0.f, 0.f);
    // top + bottom strips (contiguous)
    float2* bot = base + (long)(H2 - P) * W2 * (TT / 2);
    for (int i = threadIdx.x; i < strip; i += blockDim.x) {
        base[i] = z;
        bot[i]  = z;
    }
    // side chunks: rows P..H2-P-1, left/right P pixels = P*TT/2 float2 each
    const int ch = P * TT / 2;
    const int nrows = H2 - 2 * P;
    for (int idx = threadIdx.x; idx < nrows * 2 * ch; idx += blockDim.x) {
        int row = idx / (2 * ch);
        int rem = idx - row * (2 * ch);
        int side = rem / ch;              // 0=left 1=right
        int off  = rem - side * ch;
        float2* p = base + (long)(P + row) * W2 * (TT / 2)
                         + (side ? (W2 - P) * (TT / 2) : 0);
        p[off] = z;
    }
}

// ---------------------------------------------------------------------------
// Standalone alpha-PSP (layer 1): unpadded input -> padded bufA interior.
// ---------------------------------------------------------------------------
#define PW_PAD 53

__global__ void __launch_bounds__(128, 8) psp_kernel(const float* __restrict__ in,
                                                     float* __restrict__ out,
                                                     float r, float coef) {
    __shared__ float sm[4 * 32 * PW_PAD];
    const int lane = threadIdx.x & 31;
    const int wrp  = threadIdx.x >> 5;
    const int h    = blockIdx.x;
    const int nc   = blockIdx.y;
    float* ws = sm + wrp * 32 * PW_PAD;
    const float* g = in + (((long)nc * HHT + h) * WWD + wrp * 32) * TT;
    float* o = out + (((long)nc * AW2 + h + 2) * AW2 + (wrp * 32 + 2)) * TT;
#pragma unroll
    for (int w = 0; w < 32; ++w) {
        ws[w * PW_PAD + lane] = g[w * TT + lane];
        if (lane < TT - 32) ws[w * PW_PAD + 32 + lane] = g[w * TT + 32 + lane];
    }
    __syncwarp();
    float* row = ws + lane * PW_PAD;
    float s1 = 0.f, s2 = 0.f;
#pragma unroll
    for (int t = 0; t < TT; ++t) {
        float x = row[t];
        row[t] = coef * s2;
        s1 = fmaf(r, s1, x);
        s2 = fmaf(r, s2, r * s1);
    }
    __syncwarp();
#pragma unroll
    for (int w = 0; w < 32; ++w) {
        o[w * TT + lane] = ws[w * PW_PAD + lane];
        if (lane < TT - 32) o[w * TT + 32 + lane] = ws[w * PW_PAD + 32 + lane];
    }
}

// ---------------------------------------------------------------------------
// Fused conv(KxK, 4->4) + spike epilogue; 2-OUTPUT-ROW register blocking.
// Block (32w, 2h, n), 416 thr = 13 warps, thread = (w=lane, t-quad t0=4*wrp)
// x 2 output rows x 4 co. Per (ci,kw): K+1 input LDS.128 feed 2*K tap groups
// (each input row reused by both output rows); weight LDCs CSE across rows.
// cp.async double-buffered over ci; zero-padded input -> no bounds logic.
// ---------------------------------------------------------------------------
template <int K, int EPI, int INW2, int OUTW2, int OUTPAD>
__global__ void __launch_bounds__(416, 2)
conv_fused_kernel(const float* __restrict__ in, float* __restrict__ out,
                  float rR, float cR, float theta, float rP, float cP) {
    constexpr int WH    = 32 + (K - 1);
    constexpr int NR    = K + 1;            // input rows per stage (2 outputs)
    constexpr int STAGE = NR * WH * TP;

    extern __shared__ float sm[];
    const unsigned smem_base = (unsigned)__cvta_generic_to_shared(sm);

    const int tid  = threadIdx.x;
    const int lane = tid & 31;
    const int wrp  = tid >> 5;
    const int w0   = blockIdx.x * 32;
    const int h0   = blockIdx.y * 2;        // first output row (padded coords)
    const int n    = blockIdx.z;
    const int t0   = wrp * 4;

    // unconditional async fill: NR x WH rows of channel ci
    auto fill = [&](int buf, int ci) {
        if (lane < 25) {
            const unsigned dstb = smem_base + buf * (STAGE * 4) + lane * 8;
            const int nc = n * CHN + ci;
#pragma unroll
            for (int r = 0; r < NR; ++r) {
                const char* srcb = (const char*)(in +
                    (((long)nc * INW2 + h0 + r) * INW2 + w0) * TT) + lane * 8;
#pragma unroll
                for (int rr = 0; rr < 3; ++rr) {
                    const int wr = wrp + rr * 13;
                    if (wr < WH) {
                        asm volatile("cp.async.ca.shared.global [%0], [%1], 8;"
                                     :: "r"(dstb + (r * WH + wr) * (TP * 4)),
                                        "l"(srcb + wr * (TT * 4)) : "memory");
                    }
                }
            }
        }
        asm volatile("cp.async.commit_group;" ::: "memory");
    };

    u64 acc[2][4][2];   // [hs][co][(t0,t0+1)|(t0+2,t0+3)]
#pragma unroll
    for (int s = 0; s < 2; ++s)
#pragma unroll
        for (int c = 0; c < 4; ++c) { acc[s][c][0] = 0ull; acc[s][c][1] = 0ull; }

    fill(0, 0);
    asm volatile("cp.async.wait_group 0;" ::: "memory");
    __syncthreads();

#pragma unroll
    for (int ci = 0; ci < CHN; ++ci) {
        if (ci < CHN - 1) fill((ci + 1) & 1, ci + 1);
        const float* s_in = sm + (ci & 1) * STAGE;
#pragma unroll
        for (int kw = 0; kw < K; ++kw) {
            const float* colp = s_in + (lane + kw) * TP + t0;
            ulonglong2 iv[NR];
#pragma unroll
            for (int r = 0; r < NR; ++r)
                iv[r] = *reinterpret_cast<const ulonglong2*>(colp + r * WH * TP);
#pragma unroll
            for (int r = 0; r < NR; ++r) {
                if (r < K) {        // output row 0: kh = r
                    const int tap = (ci * K + r) * K + kw;
                    const ulonglong2 wa = cwload<K>(tap * 2);
                    const ulonglong2 wb = cwload<K>(tap * 2 + 1);
                    fma2(acc[0][0][0], iv[r].x, wa.x);
                    fma2(acc[0][0][1], iv[r].y, wa.x);
                    fma2(acc[0][1][0], iv[r].x, wa.y);
                    fma2(acc[0][1][1], iv[r].y, wa.y);
                    fma2(acc[0][2][0], iv[r].x, wb.x);
                    fma2(acc[0][2][1], iv[r].y, wb.x);
                    fma2(acc[0][3][0], iv[r].x, wb.y);
                    fma2(acc[0][3][1], iv[r].y, wb.y);
                }
                if (r >= 1) {       // output row 1: kh = r-1 (same LDC, CSE)
                    const int tap = (ci * K + (r - 1)) * K + kw;
                    const ulonglong2 wa = cwload<K>(tap * 2);
                    const ulonglong2 wb = cwload<K>(tap * 2 + 1);
                    fma2(acc[1][0][0], iv[r].x, wa.x);
                    fma2(acc[1][0][1], iv[r].y, wa.x);
                    fma2(acc[1][1][0], iv[r].x, wa.y);
                    fma2(acc[1][1][1], iv[r].y, wa.y);
                    fma2(acc[1][2][0], iv[r].x, wb.x);
                    fma2(acc[1][2][1], iv[r].y, wb.x);
                    fma2(acc[1][3][0], iv[r].x, wb.y);
                    fma2(acc[1][3][1], iv[r].y, wb.y);
                }
            }
        }
        if (ci < CHN - 1) {
            asm volatile("cp.async.wait_group 0;" ::: "memory");
            __syncthreads();
        }
    }
    __syncthreads();

    // stage conv results: s_out[(hs*4+co)][w][SOP]
    float* s_out = sm;   // overlay: 8*32*52*4 = 53248 B <= 2*STAGE (both K)
#pragma unroll
    for (int hs = 0; hs < 2; ++hs)
#pragma unroll
        for (int co = 0; co < 4; ++co) {
            float* p = s_out + ((hs * 4 + co) * 32 + lane) * SOP + t0;
            float2 a = upk(acc[hs][co][0]);
            *reinterpret_cast<float2*>(p) = a;
            if (t0 + 2 < TT) {
                float2 b = upk(acc[hs][co][1]);
                *reinterpret_cast<float2*>(p + 2) = b;
            }
        }
    __syncthreads();

    // fused spike-dynamics epilogue: 256 pixels (2hs x 4co x 32w)
    if (tid < 256) {
        const int hs = tid >> 7;
        const int co = (tid >> 5) & 3;
        const int w  = tid & 31;
        float* row = s_out + ((hs * 4 + co) * 32 + w) * SOP;
        float sd1 = 0.f, sd2 = 0.f, sp1 = 0.f, sp2 = 0.f;
#pragma unroll
        for (int t = 0; t < TT; ++t) {
            float m = fmaf(cR, sd2, row[t]);
            float s = (m >= theta) ? 1.f : 0.f;
            sd1 = fmaf(rR, sd1, s);
            sd2 = fmaf(rR, sd2, rR * sd1);
            if (EPI == 0) {
                row[t] = cP * sp2;
                sp1 = fmaf(rP, sp1, s);
                sp2 = fmaf(rP, sp2, rP * sp1);
            } else {
                row[t] = s;
            }
        }
    }
    __syncthreads();

    // structured coalesced store: float2, warp-per-w-row, 2 output rows
    if (lane < 25) {
#pragma unroll
        for (int hs = 0; hs < 2; ++hs)
#pragma unroll
            for (int co = 0; co < 4; ++co) {
                const float2* s2 = reinterpret_cast<const float2*>(
                    s_out + (hs * 4 + co) * 32 * SOP);
                float2* g2 = reinterpret_cast<float2*>(out +
                    (((long)(n * CHN + co) * OUTW2 + h0 + hs + OUTPAD) * OUTW2 +
                     (w0 + OUTPAD)) * TT);
#pragma unroll
                for (int rr = 0; rr < 3; ++rr) {
                    const int w = wrp + rr * 13;
                    if (w < 32) g2[w * (TT / 2) + lane] = s2[w * (SOP / 2) + lane];
                }
            }
    }
}

// ---------------------------------------------------------------------------

extern "C" void kernel_launch(void* const* d_in, const int* in_sizes, int n_in,
                              void* d_out, int out_size) {
    const float* x  = (const float*)d_in[0];
    const float* w1 = (const float*)d_in[1];
    const float* w2 = (const float*)d_in[2];
    float* outp = (float*)d_out;

    float *bufA, *bufB;
    cudaGetSymbolAddress((void**)&bufA, g_bufA);
    cudaGetSymbolAddress((void**)&bufB, g_bufB);
    float4* wpack;
    cudaGetSymbolAddress((void**)&wpack, g_wpack);

    const int SMEM5 = 2 * 6 * 36 * TP * 4;   // 89856 B -> 2 blocks/SM
    const int SMEM3 = 2 * 4 * 34 * TP * 4;   // 56576 B -> 2 blocks/SM
    cudaFuncSetAttribute((const void*)conv_fused_kernel<5, 0, AW2, BW2, 1>,
                         cudaFuncAttributeMaxDynamicSharedMemorySize, SMEM5);
    cudaFuncSetAttribute((const void*)conv_fused_kernel<3, 1, BW2, WWD, 0>,
                         cudaFuncAttributeMaxDynamicSharedMemorySize, SMEM3);

    const float r1  = (float)0.36787944117144233;   // exp(-1/tau1)
    const float cP1 = (float)2.718281828459045;     // e/tau1
    const float rR1 = (float)0.36787944117144233;   // exp(-1/tauRef1)
    const float cR1 = (float)(-54.365636569180902); // -scaleRef*theta1*e/tauRef1
    const float th1 = 20.0f;
    const float r2  = (float)0.6065306597126334;    // exp(-1/tau2)
    const float cP2 = (float)1.3591409142295225;    // e/tau2
    const float rR2 = (float)0.6065306597126334;    // exp(-1/tauRef2)
    const float cR2 = (float)(-54.365636569180902); // -scaleRef*theta2*e/tauRef2
    const float th2 = 40.0f;

    dim3 pgrid(HHT, NPLANE);                    // (128, 32)
    dim3 cgrid(WWD / 32, HHT / 2, NBATCH);      // (4,64,8) = 2048 blocks

    repack_kernel<<<1, 256>>>(w1, w2);
    cudaMemcpyToSymbolAsync(c_w5d, wpack, 200 * sizeof(float4), 0,
                            cudaMemcpyDeviceToDevice, 0);
    cudaMemcpyToSymbolAsync(c_w3d, wpack + 200, 72 * sizeof(float4), 0,
                            cudaMemcpyDeviceToDevice, 0);
    zero_borders<<<2 * NPLANE, 256>>>();

    psp_kernel<<<pgrid, 128>>>(x, bufA, r1, cP1);
    conv_fused_kernel<5, 0, AW2, BW2, 1><<<cgrid, 416, SMEM5>>>(bufA, bufB,
                                                    rR1, cR1, th1, r2, cP2);
    conv_fused_kernel<3, 1, BW2, WWD, 0><<<cgrid, 416, SMEM3>>>(bufB, outp,
                                                    rR2, cR2, th2, 0.f, 0.f);
}